// round 3
// baseline (speedup 1.0000x reference)
#include <cuda_runtime.h>
#include <cstdint>

#define N_TOK 131072
#define DIM   64
#define QSTG  8
#define KCB   1024

#define TM       128             // tokens per CTA
#define TKC      256             // codewords per chunk
#define NCHUNKS  32              // 8 stages * 4 chunks
#define NTHREADS 256

typedef unsigned long long ull;
typedef unsigned int uint;

// ---- dynamic smem layout (floats) ----
// sB[2] : 256 rows x 68 floats (272B padded, 16B aligned, 4-bank rotation)
// sAt   : 64 rows x 132 floats (pairs (r[2t][d], r[2t+1][d]) at [d*132 + 2*tp])
// redV  : [128][32] float ; redI : [128][32] int
#define SB_STRIDE   68
#define SB_FLOATS   (TKC * SB_STRIDE)          // 17408
#define SAT_STRIDE  132
#define SB0_F   0
#define SB1_F   SB_FLOATS
#define SAT_F   (2 * SB_FLOATS)                // 34816
#define REDV_F  (SAT_F + DIM * SAT_STRIDE)     // 34816 + 8448 = 43264
#define REDI_F  (REDV_F + TM * 32)             // + 4096
#define SMEM_FLOATS (REDI_F + TM * 32)
#define SMEM_BYTES  (SMEM_FLOATS * 4)          // 205824 B

__device__ double g_loss[QSTG];
__device__ float  g_cnorm[QSTG * KCB];

__device__ __forceinline__ void ffma2(ull& d, ull a, ull b) {
    asm("fma.rn.f32x2 %0, %1, %2, %0;" : "+l"(d) : "l"(a), "l"(b));
}
__device__ __forceinline__ ull dup2(float a) {
    ull r; unsigned u = __float_as_uint(a);
    asm("mov.b64 %0, {%1, %1};" : "=l"(r) : "r"(u));
    return r;
}
__device__ __forceinline__ float2 unpack2(ull v) {
    float2 r;
    asm("mov.b64 {%0, %1}, %2;" : "=f"(r.x), "=f"(r.y) : "l"(v));
    return r;
}
__device__ __forceinline__ void cp_async16(uint dst, const void* src) {
    asm volatile("cp.async.cg.shared.global [%0], [%1], 16;" :: "r"(dst), "l"(src));
}
__device__ __forceinline__ void cp_commit() {
    asm volatile("cp.async.commit_group;");
}
template <int N>
__device__ __forceinline__ void cp_wait() {
    asm volatile("cp.async.wait_group %0;" :: "n"(N));
}

// ---------------------------------------------------------------------------
// prep: codeword squared norms + zero loss accumulators
// ---------------------------------------------------------------------------
__global__ void prep_kernel(const float* __restrict__ cb) {
    int k = blockIdx.x * blockDim.x + threadIdx.x;
    if (k < QSTG * KCB) {
        const float* p = cb + (size_t)k * DIM;
        float s0 = 0.f, s1 = 0.f, s2 = 0.f, s3 = 0.f;
#pragma unroll
        for (int d = 0; d < DIM; d += 4) {
            s0 = __fadd_rn(s0, __fmul_rn(p[d + 0], p[d + 0]));
            s1 = __fadd_rn(s1, __fmul_rn(p[d + 1], p[d + 1]));
            s2 = __fadd_rn(s2, __fmul_rn(p[d + 2], p[d + 2]));
            s3 = __fadd_rn(s3, __fmul_rn(p[d + 3], p[d + 3]));
        }
        g_cnorm[k] = __fadd_rn(__fadd_rn(s0, s1), __fadd_rn(s2, s3));
    }
    if (blockIdx.x == 0 && threadIdx.x < QSTG) g_loss[threadIdx.x] = 0.0;
}

// ---------------------------------------------------------------------------
// fused 8-stage VQ, residual in SMEM (pairs layout), B via cp.async dbl-buffer
// ---------------------------------------------------------------------------
__global__ void __launch_bounds__(NTHREADS, 1)
vq_kernel(const float* __restrict__ x, const float* __restrict__ cb,
          float* __restrict__ out) {
    extern __shared__ float sm[];
    float* sAt  = sm + SAT_F;
    float* redV = sm + REDV_F;
    int*   redI = (int*)(sm + REDI_F);
    __shared__ int   finIdx[TM];
    __shared__ float wsum[NTHREADS / 32];

    const int tid = threadIdx.x;
    const int tpg = tid & 7;     // token-pair group: pairs tp = tpg + 8*tpi
    const int kg  = tid >> 3;    // k group 0..31 : k = kg + 32*j
    const int n0  = blockIdx.x * TM;

    uint smem_base;
    {
        void* p = (void*)sm;
        smem_base = (uint)__cvta_generic_to_shared(p);
    }

    float* out_xq  = out;
    float* out_idx = out + (size_t)N_TOK * DIM;

    // ---- build sAt from x : thread (t = tid>>1, hd = tid&1) handles 32 dims ----
    {
        const int t = tid >> 1, hd = tid & 1;
        const float4* xr = (const float4*)(x + (size_t)(n0 + t) * DIM + hd * 32);
#pragma unroll
        for (int mq = 0; mq < 8; ++mq) {
            float4 v = xr[mq];
            int d0 = hd * 32 + mq * 4;
            sAt[(d0 + 0) * SAT_STRIDE + t] = v.x;
            sAt[(d0 + 1) * SAT_STRIDE + t] = v.y;
            sAt[(d0 + 2) * SAT_STRIDE + t] = v.z;
            sAt[(d0 + 3) * SAT_STRIDE + t] = v.w;
        }
    }

    // ---- prefetch chunks 0 and 1 ----
    // chunk c = 64KB of cb starting at float offset c*256*64; smem rows padded to 272B
    {
#pragma unroll
        for (int c = 0; c < 2; ++c) {
            const char* src = (const char*)(cb + (size_t)c * TKC * DIM);
            uint buf = smem_base + (c & 1) * (SB_FLOATS * 4);
#pragma unroll
            for (int s = 0; s < 16; ++s) {
                int i = tid + NTHREADS * s;          // 16B unit index 0..4095
                int k = i >> 4, r16 = i & 15;
                cp_async16(buf + k * 272 + r16 * 16, src + (size_t)i * 16);
            }
            cp_commit();
        }
    }

    const ull neg2 = dup2(-2.0f);

    for (int q = 0; q < QSTG; ++q) {
        float bvx[8], bvy[8];
        int   bix[8], biy[8];
#pragma unroll
        for (int i = 0; i < 8; ++i) {
            bvx[i] = 3.4e38f; bvy[i] = 3.4e38f; bix[i] = 0; biy[i] = 0;
        }

        for (int ch = 0; ch < 4; ++ch) {
            const int c = q * 4 + ch;
            const float* sB = sm + ((c & 1) ? SB1_F : SB0_F);

            if (c == NCHUNKS - 1) cp_wait<0>(); else cp_wait<1>();
            __syncthreads();   // chunk c resident; sAt writers (build/update) done

            // ---- mainloop: 8 token-pairs x 8 codewords per thread ----
            ull acc[64];
#pragma unroll
            for (int i = 0; i < 64; ++i) acc[i] = 0ull;

            const float* bRow0 = sB + kg * SB_STRIDE;           // + j*32*68 + d
            const float* aRow0 = sAt + 2 * tpg;                 // + d*132 + tpi*16
#pragma unroll 4
            for (int d = 0; d < DIM; ++d) {
                const float* aR = aRow0 + d * SAT_STRIDE;
                ull a2[8];
#pragma unroll
                for (int tpi = 0; tpi < 8; ++tpi)
                    a2[tpi] = *(const ull*)(aR + 16 * tpi);
                const float* bR = bRow0 + d;
                ull b2[8];
#pragma unroll
                for (int j = 0; j < 8; ++j)
                    b2[j] = dup2(bR[j * 32 * SB_STRIDE]);
#pragma unroll
                for (int tpi = 0; tpi < 8; ++tpi)
#pragma unroll
                    for (int j = 0; j < 8; ++j)
                        ffma2(acc[tpi * 8 + j], a2[tpi], b2[j]);
            }
            __syncthreads();   // all reads of buffer (c&1) complete

            // ---- prefetch chunk c+2 into the freed buffer (overlaps epilogue) ----
            if (c + 2 < NCHUNKS) {
                const char* src = (const char*)(cb + (size_t)(c + 2) * TKC * DIM);
                uint buf = smem_base + (c & 1) * (SB_FLOATS * 4);
#pragma unroll
                for (int s = 0; s < 16; ++s) {
                    int i = tid + NTHREADS * s;
                    int k = i >> 4, r16 = i & 15;
                    cp_async16(buf + k * 272 + r16 * 16, src + (size_t)i * 16);
                }
                cp_commit();
            }

            // ---- running argmin: val = cnorm - 2*dot ----
#pragma unroll
            for (int j = 0; j < 8; ++j) {
                const int kk = ch * TKC + kg + 32 * j;          // stage-local k
                const float cn = __ldg(&g_cnorm[q * KCB + kk]);
                const ull cn2 = dup2(cn);
#pragma unroll
                for (int tpi = 0; tpi < 8; ++tpi) {
                    ull v2 = cn2;
                    ffma2(v2, acc[tpi * 8 + j], neg2);
                    float2 p = unpack2(v2);
                    bool l0 = p.x < bvx[tpi];
                    bvx[tpi] = l0 ? p.x : bvx[tpi];
                    bix[tpi] = l0 ? kk : bix[tpi];
                    bool l1 = p.y < bvy[tpi];
                    bvy[tpi] = l1 ? p.y : bvy[tpi];
                    biy[tpi] = l1 ? kk : biy[tpi];
                }
            }
        }

        // ---- stage-end: cross-thread argmin over 32 k-groups ----
#pragma unroll
        for (int tpi = 0; tpi < 8; ++tpi) {
            int tp = tpg + 8 * tpi;
            redV[(2 * tp + 0) * 32 + kg] = bvx[tpi];
            redI[(2 * tp + 0) * 32 + kg] = bix[tpi];
            redV[(2 * tp + 1) * 32 + kg] = bvy[tpi];
            redI[(2 * tp + 1) * 32 + kg] = biy[tpi];
        }
        __syncthreads();
        if (tid < TM) {
            const float* rv = redV + tid * 32;
            const int*   ri = redI + tid * 32;
            float bv = rv[0];
            int   bi = ri[0];
#pragma unroll
            for (int g = 1; g < 32; ++g) {
                float v  = rv[g];
                int   ii = ri[g];
                if (v < bv || (v == bv && ii < bi)) { bv = v; bi = ii; }
            }
            finIdx[tid] = bi;
            out_idx[(size_t)(n0 + tid) * QSTG + q] = (float)bi;
        }
        __syncthreads();

        // ---- residual update (in sAt) + commitment loss ----
        {
            const int t = tid >> 1, hd = tid & 1;
            const int idx = finIdx[t];
            const float4* c4 =
                (const float4*)(cb + (size_t)q * KCB * DIM + (size_t)idx * DIM + hd * 32);
            float ls = 0.f;
#pragma unroll
            for (int mq = 0; mq < 8; ++mq) {
                float4 cv = c4[mq];
                int d0 = hd * 32 + mq * 4;
                const float* cc = &cv.x;
#pragma unroll
                for (int e = 0; e < 4; ++e) {
                    float* slot = &sAt[(d0 + e) * SAT_STRIDE + t];
                    float nv = __fsub_rn(*slot, cc[e]);
                    *slot = nv;
                    ls = fmaf(nv, nv, ls);
                }
            }
#pragma unroll
            for (int off = 16; off; off >>= 1)
                ls += __shfl_down_sync(0xffffffff, ls, off);
            if ((tid & 31) == 0) wsum[tid >> 5] = ls;
            __syncthreads();
            if (tid == 0) {
                float tot = 0.f;
#pragma unroll
                for (int w = 0; w < NTHREADS / 32; ++w) tot += wsum[w];
                atomicAdd(&g_loss[q], (double)tot);
            }
        }
        // next loop iteration's post-wait __syncthreads orders sAt writes
    }
    __syncthreads();

    // ---- xq = x - final_residual ----
    {
        const int t = tid >> 1, hd = tid & 1;
        const float4* xr = (const float4*)(x + (size_t)(n0 + t) * DIM + hd * 32);
        float4* o4 = (float4*)(out_xq + (size_t)(n0 + t) * DIM + hd * 32);
#pragma unroll
        for (int mq = 0; mq < 8; ++mq) {
            float4 xv = xr[mq], ov;
            int d0 = hd * 32 + mq * 4;
            ov.x = __fsub_rn(xv.x, sAt[(d0 + 0) * SAT_STRIDE + t]);
            ov.y = __fsub_rn(xv.y, sAt[(d0 + 1) * SAT_STRIDE + t]);
            ov.z = __fsub_rn(xv.z, sAt[(d0 + 2) * SAT_STRIDE + t]);
            ov.w = __fsub_rn(xv.w, sAt[(d0 + 3) * SAT_STRIDE + t]);
            o4[mq] = ov;
        }
    }
}

// ---------------------------------------------------------------------------
__global__ void loss_kernel(float* __restrict__ out) {
    if (threadIdx.x < QSTG)
        out[(size_t)N_TOK * DIM + (size_t)N_TOK * QSTG + threadIdx.x] =
            (float)(g_loss[threadIdx.x] / (double)((size_t)N_TOK * DIM));
}

extern "C" void kernel_launch(void* const* d_in, const int* in_sizes, int n_in,
                              void* d_out, int out_size) {
    const float* x  = (const float*)d_in[0];
    const float* cb = (const float*)d_in[1];
    if (n_in >= 2 && in_sizes[0] == QSTG * KCB * DIM && in_sizes[1] == N_TOK * DIM) {
        const float* t = x; x = cb; cb = t;
    }
    float* out = (float*)d_out;

    cudaFuncSetAttribute(vq_kernel,
                         cudaFuncAttributeMaxDynamicSharedMemorySize, SMEM_BYTES);

    prep_kernel<<<(QSTG * KCB + 255) / 256, 256>>>(cb);
    vq_kernel<<<N_TOK / TM, NTHREADS, SMEM_BYTES>>>(x, cb, out);
    loss_kernel<<<1, 32>>>(out);
}